// round 1
// baseline (speedup 1.0000x reference)
#include <cuda_runtime.h>

#define BB 64
#define VV 2000
#define DD 16
#define CI 64
#define CO 64

// ---------------- scratch (device globals, no allocation) ----------------
__device__ float g_partG[32 * 512];          // per-block Gram partials (re,im interleaved)
__device__ float g_inv_norm;                 // 1 / ||lap||_F
__device__ float g_Zre[BB * DD * CI];        // Z = ne^H @ x   (B,16,64)
__device__ float g_Zim[BB * DD * CI];
__device__ float g_yre[(size_t)BB * VV * CI]; // y = ne @ Z  (= lap_raw @ x)
__device__ float g_yim[(size_t)BB * VV * CI];
__device__ float g_Are[(size_t)VV * CI * CO]; // A_v = ne[v]·(W0-W2)
__device__ float g_Aim[(size_t)VV * CI * CO];
__device__ float g_Cre[(size_t)VV * CI * CO]; // C_v = ne[v]·(W1+2W2) * inv_norm
__device__ float g_Cim[(size_t)VV * CI * CO];

// ---------------- 1a: Gram partials  G[d,e] = sum_v conj(ne[v,d]) ne[v,e] ----------------
__global__ void gram_partial(const float* __restrict__ ner, const float* __restrict__ nei) {
    int blk = blockIdx.x;
    int v0 = blk * 63;
    int cnt = min(63, VV - v0);
    __shared__ float sr[63 * 16], si[63 * 16];
    for (int t = threadIdx.x; t < cnt * 16; t += 256) {
        sr[t] = ner[v0 * 16 + t];
        si[t] = nei[v0 * 16 + t];
    }
    __syncthreads();
    int d = threadIdx.x >> 4, e = threadIdx.x & 15;
    float ar = 0.f, ai = 0.f;
    for (int vv = 0; vv < cnt; vv++) {
        float a = sr[vv * 16 + d], b = si[vv * 16 + d];
        float c = sr[vv * 16 + e], dd = si[vv * 16 + e];
        ar += a * c + b * dd;   // re( conj(u)*w )
        ai += a * dd - b * c;   // im( conj(u)*w )
    }
    g_partG[blk * 512 + threadIdx.x * 2]     = ar;
    g_partG[blk * 512 + threadIdx.x * 2 + 1] = ai;
}

// ---------------- 1b: reduce Gram, compute inv_norm = rsqrt(sum |G|^2) ----------------
__global__ void gram_reduce() {
    __shared__ float red[256];
    int t = threadIdx.x;
    float gr = 0.f, gi = 0.f;
    for (int blk = 0; blk < 32; blk++) {
        gr += g_partG[blk * 512 + t * 2];
        gi += g_partG[blk * 512 + t * 2 + 1];
    }
    red[t] = gr * gr + gi * gi;
    __syncthreads();
    for (int s = 128; s > 0; s >>= 1) {
        if (t < s) red[t] += red[t + s];
        __syncthreads();
    }
    if (t == 0) g_inv_norm = rsqrtf(red[0]);
}

// ---------------- 2: Z[b,d,i] = sum_v conj(ne[v,d]) * x[b,v,i]  (x real) ----------------
__global__ void __launch_bounds__(256) z_kernel(const float* __restrict__ x,
                                                const float* __restrict__ ner,
                                                const float* __restrict__ nei) {
    int b = blockIdx.y;
    int d0 = blockIdx.x * 4;
    int i = threadIdx.x & 63;
    int dl = threadIdx.x >> 6;
    __shared__ float xs[64 * 64];
    __shared__ float nr[64 * 4], ni[64 * 4];
    float ar = 0.f, ai = 0.f;
    for (int v0 = 0; v0 < VV; v0 += 64) {
        int cnt = min(64, VV - v0);
        __syncthreads();
        for (int t = threadIdx.x; t < cnt * 64; t += 256)
            xs[t] = x[(size_t)b * VV * 64 + (size_t)v0 * 64 + t];
        for (int t = threadIdx.x; t < cnt * 4; t += 256) {
            int vv = t >> 2, dd = t & 3;
            nr[t] = ner[(v0 + vv) * 16 + d0 + dd];
            ni[t] = nei[(v0 + vv) * 16 + d0 + dd];
        }
        __syncthreads();
        for (int vv = 0; vv < cnt; vv++) {
            float xv = xs[vv * 64 + i];
            ar += nr[vv * 4 + dl] * xv;
            ai -= ni[vv * 4 + dl] * xv;
        }
    }
    g_Zre[(b * 16 + d0 + dl) * 64 + i] = ar;
    g_Zim[(b * 16 + d0 + dl) * 64 + i] = ai;
}

// ---------------- 3: y[b,v,i] = sum_d ne[v,d] * Z[b,d,i]  (complex) ----------------
__global__ void __launch_bounds__(256) y_kernel(const float* __restrict__ ner,
                                                const float* __restrict__ nei) {
    int b = blockIdx.y;
    int v0 = blockIdx.x * 64;
    int vcnt = min(64, VV - v0);
    __shared__ float Zr[16 * 64], Zi[16 * 64], nr[64 * 16], ni[64 * 16];
    for (int t = threadIdx.x; t < 1024; t += 256) {
        Zr[t] = g_Zre[b * 1024 + t];
        Zi[t] = g_Zim[b * 1024 + t];
    }
    for (int t = threadIdx.x; t < vcnt * 16; t += 256) {
        nr[t] = ner[v0 * 16 + t];
        ni[t] = nei[v0 * 16 + t];
    }
    __syncthreads();
    int i = threadIdx.x & 63;
    int vb = threadIdx.x >> 6;
    float zr[16], zi[16];
#pragma unroll
    for (int d = 0; d < 16; d++) { zr[d] = Zr[d * 64 + i]; zi[d] = Zi[d * 64 + i]; }
    for (int vl = vb; vl < vcnt; vl += 4) {
        float yr = 0.f, yi = 0.f;
#pragma unroll
        for (int d = 0; d < 16; d++) {
            float a = nr[vl * 16 + d], c = ni[vl * 16 + d];
            yr += a * zr[d] - c * zi[d];
            yi += a * zi[d] + c * zr[d];
        }
        size_t o = (size_t)b * VV * 64 + (size_t)(v0 + vl) * 64 + i;
        g_yre[o] = yr;
        g_yim[o] = yi;
    }
}

// ---------------- 4: combined per-node weights ----------------
// A_v = ne[v]·(W0 - W2);  C_v = ne[v]·(W1 + 2*W2) * inv_norm   (complex contraction over d)
__global__ void __launch_bounds__(256) wcomb_kernel(const float* __restrict__ ner,
                                                    const float* __restrict__ nei,
                                                    const float* __restrict__ wr,
                                                    const float* __restrict__ wi) {
    int io = blockIdx.x * 256 + threadIdx.x;   // 0..4095 (i*64+o)
    int vstart = blockIdx.y * 100;
    float s = g_inv_norm;
    float P0r[16], P0i[16], P1r[16], P1i[16];
#pragma unroll
    for (int d = 0; d < 16; d++) {
        float r0 = wr[(d * 3 + 0) * 4096 + io];
        float r1 = wr[(d * 3 + 1) * 4096 + io];
        float r2 = wr[(d * 3 + 2) * 4096 + io];
        float i0 = wi[(d * 3 + 0) * 4096 + io];
        float i1 = wi[(d * 3 + 1) * 4096 + io];
        float i2 = wi[(d * 3 + 2) * 4096 + io];
        P0r[d] = r0 - r2;
        P0i[d] = i0 - i2;
        P1r[d] = (r1 + 2.f * r2) * s;
        P1i[d] = (i1 + 2.f * i2) * s;
    }
    __shared__ float nr[100 * 16], ni[100 * 16];
    for (int t = threadIdx.x; t < 100 * 16; t += 256) {
        nr[t] = ner[vstart * 16 + t];
        ni[t] = nei[vstart * 16 + t];
    }
    __syncthreads();
    for (int vl = 0; vl < 100; vl++) {
        float Ar = 0.f, Ai = 0.f, Cr = 0.f, Ci = 0.f;
#pragma unroll
        for (int d = 0; d < 16; d++) {
            float a = nr[vl * 16 + d], b = ni[vl * 16 + d];
            Ar += a * P0r[d] - b * P0i[d];
            Ai += a * P0i[d] + b * P0r[d];
            Cr += a * P1r[d] - b * P1i[d];
            Ci += a * P1i[d] + b * P1r[d];
        }
        size_t off = (size_t)(vstart + vl) * 4096 + io;
        g_Are[off] = Ar;
        g_Aim[off] = Ai;
        g_Cre[off] = Cr;
        g_Cim[off] = Ci;
    }
}

// ---------------- 5: final per-node GEMM + bias + interleave ----------------
// out_re[b,v,o] = sum_i x*A_re + y_re*C_re - y_im*C_im  + bias_re
// out_im[b,v,o] = sum_i x*A_im + y_re*C_im + y_im*C_re  + bias_im
__global__ void __launch_bounds__(256) out_kernel(const float* __restrict__ x,
                                                  const float* __restrict__ ner,
                                                  const float* __restrict__ nei,
                                                  const float* __restrict__ bre,
                                                  const float* __restrict__ bim,
                                                  float* __restrict__ out) {
    extern __shared__ float sm[];
    float* Ar = sm;            // 4096
    float* Ai = sm + 4096;
    float* Cr = sm + 8192;
    float* Ci = sm + 12288;
    float* xs = sm + 16384;    // 4096 : [b][i]
    float* yr = sm + 20480;
    float* yi = sm + 24576;
    float* br = sm + 28672;    // 64
    float* bi = sm + 28736;

    int v = blockIdx.x;
    size_t vo = (size_t)v * 4096;
    for (int t = threadIdx.x; t < 4096; t += 256) {
        Ar[t] = g_Are[vo + t];
        Ai[t] = g_Aim[vo + t];
        Cr[t] = g_Cre[vo + t];
        Ci[t] = g_Cim[vo + t];
        int b = t >> 6, i = t & 63;
        size_t xoff = (size_t)b * (VV * 64) + (size_t)v * 64 + i;
        xs[t] = x[xoff];
        yr[t] = g_yre[xoff];
        yi[t] = g_yim[xoff];
    }
    if (threadIdx.x < 64) {
        int o = threadIdx.x;
        float r = 0.f, m = 0.f;
#pragma unroll
        for (int d = 0; d < 16; d++) {
            float a = ner[v * 16 + d], b2 = nei[v * 16 + d];
            float pr = bre[d * 64 + o], pi = bim[d * 64 + o];
            r += a * pr - b2 * pi;
            m += a * pi + b2 * pr;
        }
        br[o] = r;
        bi[o] = m;
    }
    __syncthreads();

    int og = (threadIdx.x & 15) * 4;
    int bg = (threadIdx.x >> 4) * 4;
    float accR[4][4] = {}, accI[4][4] = {};
#pragma unroll 4
    for (int i = 0; i < 64; i++) {
        float xv[4], yrv[4], yiv[4];
#pragma unroll
        for (int b = 0; b < 4; b++) {
            int base = (bg + b) * 64 + i;
            xv[b] = xs[base];
            yrv[b] = yr[base];
            yiv[b] = yi[base];
        }
        float4 a4 = *(const float4*)&Ar[i * 64 + og];
        float4 b4 = *(const float4*)&Ai[i * 64 + og];
        float4 c4 = *(const float4*)&Cr[i * 64 + og];
        float4 d4 = *(const float4*)&Ci[i * 64 + og];
        float ar_[4] = {a4.x, a4.y, a4.z, a4.w};
        float ai_[4] = {b4.x, b4.y, b4.z, b4.w};
        float cr_[4] = {c4.x, c4.y, c4.z, c4.w};
        float ci_[4] = {d4.x, d4.y, d4.z, d4.w};
#pragma unroll
        for (int b = 0; b < 4; b++) {
#pragma unroll
            for (int oo = 0; oo < 4; oo++) {
                accR[b][oo] += xv[b] * ar_[oo] + yrv[b] * cr_[oo] - yiv[b] * ci_[oo];
                accI[b][oo] += xv[b] * ai_[oo] + yrv[b] * ci_[oo] + yiv[b] * cr_[oo];
            }
        }
    }
#pragma unroll
    for (int b = 0; b < 4; b++) {
        int bidx = bg + b;
        size_t ob = ((size_t)bidx * VV + v) * 128 + 2 * og;
        float buf[8];
#pragma unroll
        for (int oo = 0; oo < 4; oo++) {
            buf[2 * oo]     = accR[b][oo] + br[og + oo];
            buf[2 * oo + 1] = accI[b][oo] + bi[og + oo];
        }
        *(float4*)&out[ob]     = *(float4*)&buf[0];
        *(float4*)&out[ob + 4] = *(float4*)&buf[4];
    }
}

extern "C" void kernel_launch(void* const* d_in, const int* in_sizes, int n_in,
                              void* d_out, int out_size) {
    const float* x   = (const float*)d_in[0];
    const float* ner = (const float*)d_in[1];
    const float* nei = (const float*)d_in[2];
    const float* wr  = (const float*)d_in[3];
    const float* wi  = (const float*)d_in[4];
    const float* bre = (const float*)d_in[5];
    const float* bim = (const float*)d_in[6];
    float* out = (float*)d_out;

    cudaFuncSetAttribute(out_kernel, cudaFuncAttributeMaxDynamicSharedMemorySize, 28800 * 4);

    gram_partial<<<32, 256>>>(ner, nei);
    gram_reduce<<<1, 256>>>();
    z_kernel<<<dim3(4, BB), 256>>>(x, ner, nei);
    y_kernel<<<dim3(32, BB), 256>>>(ner, nei);
    wcomb_kernel<<<dim3(16, 20), 256>>>(ner, nei, wr, wi);
    out_kernel<<<VV, 256, 28800 * 4>>>(x, ner, nei, bre, bim, out);
}